// round 10
// baseline (speedup 1.0000x reference)
#include <cuda_runtime.h>
#include <math.h>

#define DD   128
#define HH   8
#define EDIM 16
#define NMAX 50000
#define EMAX 800000
#define DEGPAD 51200
#define FULLMASK 0xffffffffu
#define FGRID 444
#define FWARPS (FGRID * 4)

typedef unsigned long long ull;
union F2U { ull u; float2 f; };

__device__ __forceinline__ void fma2(ull &d, ull a, ull b) {
    asm("fma.rn.f32x2 %0, %1, %2, %0;" : "+l"(d) : "l"(a), "l"(b));
}

// ---------------- scratch ----------------
__device__ float g_xl[NMAX * DD];
__device__ float g_xr[NMAX * DD];
__device__ float g_Wp[64 * 512];
__device__ int   g_deg[DEGPAD];
__device__ int   g_off[NMAX + 1];
__device__ int   g_woff[NMAX + 1];
__device__ int   g_perm[EMAX];
__device__ int   g_bsum[64];
__device__ int   g_bpre[64];
__device__ float g_sum[DD];
__device__ float g_sumsq[DD];
__device__ float g_scale[DD];
__device__ float g_shift[DD];

// ---------------- init ----------------
__global__ void k_zero(int n) {
    int i = blockIdx.x * blockDim.x + threadIdx.x;
    int stride = gridDim.x * blockDim.x;
    for (int j = i; j < DEGPAD; j += stride) g_deg[j] = 0;
    if (i < DD) { g_sum[i] = 0.f; g_sumsq[i] = 0.f; }
}

// ---------------- CSR hist ----------------
__global__ void k_hist(const int* __restrict__ ei, int E) {
    int e = blockIdx.x * blockDim.x + threadIdx.x;
    if (e < E) atomicAdd(&g_deg[ei[E + e]], 1);
}

// ---------------- pack W (k-pair interleaved) ----------------
__global__ void k_packW(const float* __restrict__ Wl, const float* __restrict__ Wr) {
    int i = blockIdx.x * blockDim.x + threadIdx.x;
    if (i >= 64 * 512) return;
    int q  = i & 3;
    int tc = (i >> 2) & 31;
    int f  = (i >> 7) & 3;
    int kp = i >> 9;
    int m = f >> 1;
    int ci = ((f & 1) << 1) | (q >> 1);
    int ki = q & 1;
    int c = tc * 4 + ci;
    int k = kp * 2 + ki;
    g_Wp[i] = (m ? Wr : Wl)[k * DD + c];
}

// ---------------- node transform: warp-split, 8 rows/warp, 32-row tile -------
// 8 warps: mat = g&1, tr = g>>1 -> rows [8tr..8tr+7]. 2 CTA/SM.
__global__ __launch_bounds__(256, 2) void k_node(
    const int* __restrict__ x, const float* __restrict__ emb,
    const float* __restrict__ bl, const float* __restrict__ br, int n)
{
    __shared__ float hs[2][32 * DD];   // 32 KB ping-pong
    int tid = threadIdx.x;
    int tc = tid & 31;
    int g  = tid >> 5;
    int mat = g & 1;
    int tr  = g >> 1;                   // 0..3
    float4 bv = ((const float4*)(mat ? br : bl))[tc];
    float* gout = mat ? g_xr : g_xl;
    const float SQ = 11.313708498984761f;
    int ntiles = (n + 31) >> 5;

    int t = blockIdx.x;
    if (t >= ntiles) return;
    int cur = 0;

    // stage tile t
    {
        int base = t * 32;
        int nrows = min(32, n - base);
        for (int i = tid; i < 32 * 32; i += 256) {
            int r = i >> 5, c4 = i & 31;
            float4 v = make_float4(0.f, 0.f, 0.f, 0.f);
            if (r < nrows) {
                const float4* src = (const float4*)(emb + (size_t)x[base + r] * DD);
                v = src[c4];
                v.x *= SQ; v.y *= SQ; v.z *= SQ; v.w *= SQ;
            }
            ((float4*)hs[cur])[i] = v;
        }
    }
    __syncthreads();

    while (t < ntiles) {
        int tn = t + gridDim.x;
        if (tn < ntiles) {
            int base = tn * 32;
            int nrows = min(32, n - base);
            for (int i = tid; i < 32 * 32; i += 256) {
                int r = i >> 5, c4 = i & 31;
                float4 v = make_float4(0.f, 0.f, 0.f, 0.f);
                if (r < nrows) {
                    const float4* src = (const float4*)(emb + (size_t)x[base + r] * DD);
                    v = src[c4];
                    v.x *= SQ; v.y *= SQ; v.z *= SQ; v.w *= SQ;
                }
                ((float4*)hs[cur ^ 1])[i] = v;
            }
        }

        ull acc[8][4];
        #pragma unroll
        for (int r = 0; r < 8; r++)
            #pragma unroll
            for (int c = 0; c < 4; c++) acc[r][c] = 0ull;

        const float* hbase = hs[cur] + tr * 8 * DD;
        const float* wbase = g_Wp + mat * 256 + tc * 4;
        #pragma unroll 2
        for (int kp = 0; kp < 64; kp++) {
            ulonglong2 L0 = *(const ulonglong2*)(wbase + kp * 512);
            ulonglong2 L1 = *(const ulonglong2*)(wbase + kp * 512 + 128);
            ull w[4] = { L0.x, L0.y, L1.x, L1.y };
            #pragma unroll
            for (int r = 0; r < 8; r++) {
                ull hp = *(const ull*)(hbase + r * DD + 2 * kp);
                #pragma unroll
                for (int c = 0; c < 4; c++)
                    fma2(acc[r][c], hp, w[c]);
            }
        }

        int base = t * 32;
        #pragma unroll
        for (int r = 0; r < 8; r++) {
            int row = base + tr * 8 + r;
            if (row < n) {
                F2U t0, t1, t2, t3;
                t0.u = acc[r][0]; t1.u = acc[r][1];
                t2.u = acc[r][2]; t3.u = acc[r][3];
                float4 o = make_float4(t0.f.x + t0.f.y + bv.x, t1.f.x + t1.f.y + bv.y,
                                       t2.f.x + t2.f.y + bv.z, t3.f.x + t3.f.y + bv.w);
                *(float4*)(gout + (size_t)row * DD + tc * 4) = o;
            }
        }
        __syncthreads();
        cur ^= 1;
        t = tn;
    }
}

// ---------------- CSR scan ----------------
__global__ __launch_bounds__(256) void k_bsum() {
    __shared__ int ws[8];
    int b = blockIdx.x, tid = threadIdx.x;
    int4 d = ((const int4*)g_deg)[b * 256 + tid];
    int s = d.x + d.y + d.z + d.w;
    #pragma unroll
    for (int o = 16; o > 0; o >>= 1) s += __shfl_xor_sync(FULLMASK, s, o);
    if ((tid & 31) == 0) ws[tid >> 5] = s;
    __syncthreads();
    if (tid == 0) {
        int t = 0;
        #pragma unroll
        for (int i = 0; i < 8; i++) t += ws[i];
        g_bsum[b] = t;
    }
}

__global__ void k_bscan(int nb) {
    __shared__ int ws[2];
    int t = threadIdx.x;
    int lane = t & 31, w = t >> 5;
    int v = (t < nb) ? g_bsum[t] : 0;
    int s = v;
    #pragma unroll
    for (int o = 1; o < 32; o <<= 1) {
        int u = __shfl_up_sync(FULLMASK, s, o);
        if (lane >= o) s += u;
    }
    if (lane == 31) ws[w] = s;
    __syncthreads();
    int add = (w == 1) ? ws[0] : 0;
    g_bpre[t] = s - v + add;
}

__global__ __launch_bounds__(256) void k_off(int n) {
    __shared__ int wtot[8], wpre[8];
    int b = blockIdx.x, tid = threadIdx.x;
    int lane = tid & 31, w = tid >> 5;
    int4 d = ((const int4*)g_deg)[b * 256 + tid];
    int s0 = d.x, s01 = s0 + d.y, s012 = s01 + d.z;
    int tsum = s012 + d.w;
    int inc = tsum;
    #pragma unroll
    for (int o = 1; o < 32; o <<= 1) {
        int u = __shfl_up_sync(FULLMASK, inc, o);
        if (lane >= o) inc += u;
    }
    if (lane == 31) wtot[w] = inc;
    __syncthreads();
    if (w == 0 && lane < 8) {
        int v = wtot[lane];
        int s = v;
        #pragma unroll
        for (int o = 1; o < 8; o <<= 1) {
            int u = __shfl_up_sync(0xffu, s, o);
            if (lane >= o) s += u;
        }
        wpre[lane] = s - v;
    }
    __syncthreads();
    int excl = inc - tsum + wpre[w] + g_bpre[b];
    int idx = b * 1024 + tid * 4;
    if (idx     <= n) { g_off[idx]     = excl;        g_woff[idx]     = excl; }
    if (idx + 1 <= n) { g_off[idx + 1] = excl + s0;   g_woff[idx + 1] = excl + s0; }
    if (idx + 2 <= n) { g_off[idx + 2] = excl + s01;  g_woff[idx + 2] = excl + s01; }
    if (idx + 3 <= n) { g_off[idx + 3] = excl + s012; g_woff[idx + 3] = excl + s012; }
}

__global__ void k_scatter(const int* __restrict__ ei, int E) {
    int e = blockIdx.x * blockDim.x + threadIdx.x;
    if (e < E) {
        int dst = ei[E + e];
        int pos = atomicAdd(&g_woff[dst], 1);
        g_perm[pos] = e;
    }
}

// ---------------- fused score + softmax + aggregation + BN stats -------------
// Warp per contiguous node range; dense CSR position stream; software-pipelined
// block staging: LDG next block -> regs at iter start, compute current from
// smem, STS at iter end (LDG latency hides under compute).
__device__ __forceinline__ void edge_compute(
    const float* eew, float4 xlv, float4 xrv, float4 a4,
    const ull (&wreg)[8][4], float4 &acc, float &ds)
{
    ull p0 = 0, p1 = 0, p2 = 0, p3 = 0;
    #pragma unroll
    for (int dp = 0; dp < 8; dp++) {
        ull a = *(const ull*)(eew + 2 * dp);   // smem broadcast
        fma2(p0, a, wreg[dp][0]);
        fma2(p1, a, wreg[dp][1]);
        fma2(p2, a, wreg[dp][2]);
        fma2(p3, a, wreg[dp][3]);
    }
    F2U u0, u1, u2, u3;
    u0.u = p0; u1.u = p1; u2.u = p2; u3.u = p3;
    float mx = xlv.x + xrv.x + u0.f.x + u0.f.y;
    float my = xlv.y + xrv.y + u1.f.x + u1.f.y;
    float mz = xlv.z + xrv.z + u2.f.x + u2.f.y;
    float mw = xlv.w + xrv.w + u3.f.x + u3.f.y;
    mx = mx > 0.f ? mx : 0.2f * mx;
    my = my > 0.f ? my : 0.2f * my;
    mz = mz > 0.f ? mz : 0.2f * mz;
    mw = mw > 0.f ? mw : 0.2f * mw;
    float s = mx * a4.x + my * a4.y + mz * a4.z + mw * a4.w;
    s += __shfl_xor_sync(FULLMASK, s, 1);
    s += __shfl_xor_sync(FULLMASK, s, 2);
    float w = __expf(s);
    ds += w;
    acc.x = fmaf(w, xlv.x, acc.x);
    acc.y = fmaf(w, xlv.y, acc.y);
    acc.z = fmaf(w, xlv.z, acc.z);
    acc.w = fmaf(w, xlv.w, acc.w);
}

#define FINALIZE_NODE()                                                        \
    {                                                                          \
        float invd = (ds > 0.f) ? 1.f / ds : 0.f;                              \
        float4 o = make_float4(fmaf(acc.x, invd, b4.x), fmaf(acc.y, invd, b4.y),\
                               fmaf(acc.z, invd, b4.z), fmaf(acc.w, invd, b4.w));\
        *(float4*)(out + (size_t)vcur * DD + col) = o;                         \
        sacc.x += o.x; sacc.y += o.y; sacc.z += o.z; sacc.w += o.w;            \
        qacc.x = fmaf(o.x, o.x, qacc.x); qacc.y = fmaf(o.y, o.y, qacc.y);      \
        qacc.z = fmaf(o.z, o.z, qacc.z); qacc.w = fmaf(o.w, o.w, qacc.w);      \
    }

#define ADVANCE_NODES()                                                        \
    while (blk + j == vend) {                                                  \
        FINALIZE_NODE();                                                       \
        vcur++;                                                                \
        vend = g_off[vcur + 1];                                                \
        xrv = *(const float4*)(g_xr + (size_t)vcur * DD + col);                \
        acc = make_float4(0.f, 0.f, 0.f, 0.f); ds = 0.f;                       \
    }

#define EDGE_STAGE(Q)                                                          \
    {                                                                          \
        ADVANCE_NODES();                                                       \
        float4 xlv = Q;                                                        \
        if (j + 4 < m) {                                                       \
            int s4i = __shfl_sync(FULLMASK, sCur, j + 4);                      \
            Q = *(const float4*)(g_xl + (size_t)s4i * DD + col);               \
        }                                                                      \
        edge_compute(sewc + j * EDIM, xlv, xrv, a4, wreg, acc, ds);            \
        j++;                                                                   \
    }

__global__ __launch_bounds__(128, 3) void k_fused(
    const int* __restrict__ ei, const float* __restrict__ ew,
    const float* __restrict__ We, const float* __restrict__ att,
    const float* __restrict__ bias, float* __restrict__ out, int n, int npw)
{
    __shared__ float sew_all[4][2][32 * EDIM];   // 16 KB
    __shared__ float ssum[4][DD], ssq[4][DD];    // 4 KB
    int lane = threadIdx.x & 31;
    int wid  = threadIdx.x >> 5;
    int gw = blockIdx.x * 4 + wid;
    int col = lane * 4;

    ull wreg[8][4];
    #pragma unroll
    for (int dp = 0; dp < 8; dp++) {
        #pragma unroll
        for (int c = 0; c < 4; c++) {
            F2U t;
            t.f.x = __ldg(We + (2 * dp)     * DD + col + c);
            t.f.y = __ldg(We + (2 * dp + 1) * DD + col + c);
            wreg[dp][c] = t.u;
        }
    }
    float4 a4 = ((const float4*)att)[lane];
    float4 b4 = ((const float4*)bias)[lane];
    float4 sacc = make_float4(0.f, 0.f, 0.f, 0.f);
    float4 qacc = make_float4(0.f, 0.f, 0.f, 0.f);

    int v0 = gw * npw;
    int v1 = min(n, v0 + npw);

    if (v0 < v1) {
        int p0 = g_off[v0], p1 = g_off[v1];
        int vcur = v0;
        int vend = g_off[v0 + 1];
        float4 xrv = *(const float4*)(g_xr + (size_t)vcur * DD + col);
        float4 acc = make_float4(0.f, 0.f, 0.f, 0.f);
        float ds = 0.f;
        int parity = 0;
        int sCur = 0;

        // stage block 0 synchronously
        {
            int m0 = min(32, p1 - p0);
            if (lane < m0) {
                int eL = g_perm[p0 + lane];
                sCur = __ldg(ei + eL);
                const float4* src = (const float4*)(ew + (size_t)eL * EDIM);
                float4* dst = (float4*)(&sew_all[wid][0][lane * EDIM]);
                dst[0] = src[0]; dst[1] = src[1]; dst[2] = src[2]; dst[3] = src[3];
            }
            __syncwarp();
        }

        for (int blk = p0; blk < p1; blk += 32) {
            int m = min(32, p1 - blk);
            // prefetch next block into registers (LDG issued, waited at STS below)
            int sNxt = 0, mn = 0;
            float4 nb0 = make_float4(0,0,0,0), nb1 = nb0, nb2 = nb0, nb3 = nb0;
            if (blk + 32 < p1) {
                mn = min(32, p1 - (blk + 32));
                if (lane < mn) {
                    int eL = g_perm[blk + 32 + lane];
                    sNxt = __ldg(ei + eL);
                    const float4* src = (const float4*)(ew + (size_t)eL * EDIM);
                    nb0 = src[0]; nb1 = src[1]; nb2 = src[2]; nb3 = src[3];
                }
            }

            // compute current block
            const float* sewc = &sew_all[wid][parity][0];
            int s0 = __shfl_sync(FULLMASK, sCur, 0);
            int s1 = __shfl_sync(FULLMASK, sCur, 1);
            int s2 = __shfl_sync(FULLMASK, sCur, 2);
            int s3 = __shfl_sync(FULLMASK, sCur, 3);
            float4 xq0 = *(const float4*)(g_xl + (size_t)s0 * DD + col);
            float4 xq1 = *(const float4*)(g_xl + (size_t)s1 * DD + col);
            float4 xq2 = *(const float4*)(g_xl + (size_t)s2 * DD + col);
            float4 xq3 = *(const float4*)(g_xl + (size_t)s3 * DD + col);

            int j = 0;
            while (j < m) {
                EDGE_STAGE(xq0)
                if (j >= m) break;
                EDGE_STAGE(xq1)
                if (j >= m) break;
                EDGE_STAGE(xq2)
                if (j >= m) break;
                EDGE_STAGE(xq3)
            }

            // commit next block to the other buffer (LDG data arrived during compute)
            if (lane < mn) {
                float4* dst = (float4*)(&sew_all[wid][parity ^ 1][lane * EDIM]);
                dst[0] = nb0; dst[1] = nb1; dst[2] = nb2; dst[3] = nb3;
            }
            __syncwarp();
            sCur = sNxt;
            parity ^= 1;
        }

        // finalize in-flight node + trailing zero-degree nodes
        while (vcur < v1) {
            FINALIZE_NODE();
            vcur++;
            acc = make_float4(0.f, 0.f, 0.f, 0.f); ds = 0.f;
        }
    }

    // block-level BN stats reduction
    *(float4*)&ssum[wid][col] = sacc;
    *(float4*)&ssq[wid][col]  = qacc;
    __syncthreads();
    int ch = threadIdx.x;
    float s = ssum[0][ch] + ssum[1][ch] + ssum[2][ch] + ssum[3][ch];
    float q = ssq[0][ch]  + ssq[1][ch]  + ssq[2][ch]  + ssq[3][ch];
    atomicAdd(&g_sum[ch], s);
    atomicAdd(&g_sumsq[ch], q);
}

// ---------------- BN finalize + apply ----------------
__global__ void k_finalize(const float* __restrict__ gamma, const float* __restrict__ beta, int n) {
    int t = threadIdx.x;
    if (t < DD) {
        float invn = 1.f / (float)n;
        float mean = g_sum[t] * invn;
        float var  = g_sumsq[t] * invn - mean * mean;
        if (var < 0.f) var = 0.f;
        float inv = rsqrtf(var + 1e-5f);
        float sc = gamma[t] * inv;
        g_scale[t] = sc;
        g_shift[t] = beta[t] - mean * sc;
    }
}

__global__ void k_apply(float* __restrict__ out, int n) {
    int i = blockIdx.x * blockDim.x + threadIdx.x;
    int total = n * (DD / 4);
    if (i < total) {
        float4 v = ((float4*)out)[i];
        float4 sc = ((float4*)g_scale)[i & 31];
        float4 sh = ((float4*)g_shift)[i & 31];
        float yx = fmaf(v.x, sc.x, sh.x);
        float yy = fmaf(v.y, sc.y, sh.y);
        float yz = fmaf(v.z, sc.z, sh.z);
        float yw = fmaf(v.w, sc.w, sh.w);
        v.x = yx > 0.f ? yx : 0.01f * yx;
        v.y = yy > 0.f ? yy : 0.01f * yy;
        v.z = yz > 0.f ? yz : 0.01f * yz;
        v.w = yw > 0.f ? yw : 0.01f * yw;
        ((float4*)out)[i] = v;
    }
}

// ---------------- launch ----------------
extern "C" void kernel_launch(void* const* d_in, const int* in_sizes, int n_in,
                              void* d_out, int out_size)
{
    const int*   x     = (const int*)  d_in[0];
    const int*   ei    = (const int*)  d_in[1];
    const float* ew    = (const float*)d_in[2];
    const float* emb   = (const float*)d_in[3];
    const float* Wl    = (const float*)d_in[4];
    const float* bl    = (const float*)d_in[5];
    const float* Wr    = (const float*)d_in[6];
    const float* br    = (const float*)d_in[7];
    const float* att   = (const float*)d_in[8];
    const float* We    = (const float*)d_in[9];
    const float* bias  = (const float*)d_in[10];
    const float* gamma = (const float*)d_in[11];
    const float* beta  = (const float*)d_in[12];
    float* out = (float*)d_out;

    int n = in_sizes[0];
    int E = in_sizes[1] / 2;
    int nb = (n + 1023) / 1024;
    int npw = (n + FWARPS - 1) / FWARPS;

    k_zero<<<96, 256>>>(n);
    k_hist<<<(E + 255) / 256, 256>>>(ei, E);
    k_packW<<<128, 256>>>(Wl, Wr);

    k_node<<<296, 256>>>(x, emb, bl, br, n);   // 4th launch -> ncu capture

    k_bsum<<<nb, 256>>>();
    k_bscan<<<1, 64>>>(nb);
    k_off<<<nb, 256>>>(n);
    k_scatter<<<(E + 255) / 256, 256>>>(ei, E);

    k_fused<<<FGRID, 128>>>(ei, ew, We, att, bias, out, n, npw);

    k_finalize<<<1, 128>>>(gamma, beta, n);
    k_apply<<<(n * (DD / 4) + 255) / 256, 256>>>(out, n);
}

// round 11
// speedup vs baseline: 1.1575x; 1.1575x over previous
#include <cuda_runtime.h>
#include <math.h>

#define DD   128
#define HH   8
#define EDIM 16
#define NMAX 50000
#define EMAX 800000
#define DEGPAD 51200
#define FULLMASK 0xffffffffu

typedef unsigned long long ull;
union F2U { ull u; float2 f; };

__device__ __forceinline__ void fma2(ull &d, ull a, ull b) {
    asm("fma.rn.f32x2 %0, %1, %2, %0;" : "+l"(d) : "l"(a), "l"(b));
}

// ---------------- scratch ----------------
__device__ float g_xl[NMAX * DD];
__device__ float g_xr[NMAX * DD];
__device__ float g_Wp[64 * 512];
__device__ int   g_deg[DEGPAD];
__device__ int   g_off[NMAX + 1];
__device__ int   g_woff[NMAX + 1];
__device__ int   g_perm[EMAX];
__device__ int   g_bsum[64];
__device__ int   g_bpre[64];
__device__ float g_sum[DD];
__device__ float g_sumsq[DD];
__device__ float g_scale[DD];
__device__ float g_shift[DD];

// ---------------- init ----------------
__global__ void k_zero(int n) {
    int i = blockIdx.x * blockDim.x + threadIdx.x;
    int stride = gridDim.x * blockDim.x;
    for (int j = i; j < DEGPAD; j += stride) g_deg[j] = 0;
    if (i < DD) { g_sum[i] = 0.f; g_sumsq[i] = 0.f; }
}

// ---------------- CSR hist ----------------
__global__ void k_hist(const int* __restrict__ ei, int E) {
    int e = blockIdx.x * blockDim.x + threadIdx.x;
    if (e < E) atomicAdd(&g_deg[ei[E + e]], 1);
}

// ---------------- pack W (k-pair interleaved) ----------------
__global__ void k_packW(const float* __restrict__ Wl, const float* __restrict__ Wr) {
    int i = blockIdx.x * blockDim.x + threadIdx.x;
    if (i >= 64 * 512) return;
    int q  = i & 3;
    int tc = (i >> 2) & 31;
    int f  = (i >> 7) & 3;
    int kp = i >> 9;
    int m = f >> 1;
    int ci = ((f & 1) << 1) | (q >> 1);
    int ki = q & 1;
    int c = tc * 4 + ci;
    int k = kp * 2 + ki;
    g_Wp[i] = (m ? Wr : Wl)[k * DD + c];
}

// ---------------- node transform: warp-split, 8 rows/warp, 32-row tile -------
__global__ __launch_bounds__(256, 2) void k_node(
    const int* __restrict__ x, const float* __restrict__ emb,
    const float* __restrict__ bl, const float* __restrict__ br, int n)
{
    __shared__ float hs[2][32 * DD];   // 32 KB ping-pong
    int tid = threadIdx.x;
    int tc = tid & 31;
    int g  = tid >> 5;
    int mat = g & 1;
    int tr  = g >> 1;                   // 0..3
    float4 bv = ((const float4*)(mat ? br : bl))[tc];
    float* gout = mat ? g_xr : g_xl;
    const float SQ = 11.313708498984761f;
    int ntiles = (n + 31) >> 5;

    int t = blockIdx.x;
    if (t >= ntiles) return;
    int cur = 0;

    {
        int base = t * 32;
        int nrows = min(32, n - base);
        for (int i = tid; i < 32 * 32; i += 256) {
            int r = i >> 5, c4 = i & 31;
            float4 v = make_float4(0.f, 0.f, 0.f, 0.f);
            if (r < nrows) {
                const float4* src = (const float4*)(emb + (size_t)x[base + r] * DD);
                v = src[c4];
                v.x *= SQ; v.y *= SQ; v.z *= SQ; v.w *= SQ;
            }
            ((float4*)hs[cur])[i] = v;
        }
    }
    __syncthreads();

    while (t < ntiles) {
        int tn = t + gridDim.x;
        if (tn < ntiles) {
            int base = tn * 32;
            int nrows = min(32, n - base);
            for (int i = tid; i < 32 * 32; i += 256) {
                int r = i >> 5, c4 = i & 31;
                float4 v = make_float4(0.f, 0.f, 0.f, 0.f);
                if (r < nrows) {
                    const float4* src = (const float4*)(emb + (size_t)x[base + r] * DD);
                    v = src[c4];
                    v.x *= SQ; v.y *= SQ; v.z *= SQ; v.w *= SQ;
                }
                ((float4*)hs[cur ^ 1])[i] = v;
            }
        }

        ull acc[8][4];
        #pragma unroll
        for (int r = 0; r < 8; r++)
            #pragma unroll
            for (int c = 0; c < 4; c++) acc[r][c] = 0ull;

        const float* hbase = hs[cur] + tr * 8 * DD;
        const float* wbase = g_Wp + mat * 256 + tc * 4;
        #pragma unroll 2
        for (int kp = 0; kp < 64; kp++) {
            ulonglong2 L0 = *(const ulonglong2*)(wbase + kp * 512);
            ulonglong2 L1 = *(const ulonglong2*)(wbase + kp * 512 + 128);
            ull w[4] = { L0.x, L0.y, L1.x, L1.y };
            #pragma unroll
            for (int r = 0; r < 8; r++) {
                ull hp = *(const ull*)(hbase + r * DD + 2 * kp);
                #pragma unroll
                for (int c = 0; c < 4; c++)
                    fma2(acc[r][c], hp, w[c]);
            }
        }

        int base = t * 32;
        #pragma unroll
        for (int r = 0; r < 8; r++) {
            int row = base + tr * 8 + r;
            if (row < n) {
                F2U t0, t1, t2, t3;
                t0.u = acc[r][0]; t1.u = acc[r][1];
                t2.u = acc[r][2]; t3.u = acc[r][3];
                float4 o = make_float4(t0.f.x + t0.f.y + bv.x, t1.f.x + t1.f.y + bv.y,
                                       t2.f.x + t2.f.y + bv.z, t3.f.x + t3.f.y + bv.w);
                *(float4*)(gout + (size_t)row * DD + tc * 4) = o;
            }
        }
        __syncthreads();
        cur ^= 1;
        t = tn;
    }
}

// ---------------- CSR scan ----------------
__global__ __launch_bounds__(256) void k_bsum() {
    __shared__ int ws[8];
    int b = blockIdx.x, tid = threadIdx.x;
    int4 d = ((const int4*)g_deg)[b * 256 + tid];
    int s = d.x + d.y + d.z + d.w;
    #pragma unroll
    for (int o = 16; o > 0; o >>= 1) s += __shfl_xor_sync(FULLMASK, s, o);
    if ((tid & 31) == 0) ws[tid >> 5] = s;
    __syncthreads();
    if (tid == 0) {
        int t = 0;
        #pragma unroll
        for (int i = 0; i < 8; i++) t += ws[i];
        g_bsum[b] = t;
    }
}

__global__ void k_bscan(int nb) {
    __shared__ int ws[2];
    int t = threadIdx.x;
    int lane = t & 31, w = t >> 5;
    int v = (t < nb) ? g_bsum[t] : 0;
    int s = v;
    #pragma unroll
    for (int o = 1; o < 32; o <<= 1) {
        int u = __shfl_up_sync(FULLMASK, s, o);
        if (lane >= o) s += u;
    }
    if (lane == 31) ws[w] = s;
    __syncthreads();
    int add = (w == 1) ? ws[0] : 0;
    g_bpre[t] = s - v + add;
}

__global__ __launch_bounds__(256) void k_off(int n) {
    __shared__ int wtot[8], wpre[8];
    int b = blockIdx.x, tid = threadIdx.x;
    int lane = tid & 31, w = tid >> 5;
    int4 d = ((const int4*)g_deg)[b * 256 + tid];
    int s0 = d.x, s01 = s0 + d.y, s012 = s01 + d.z;
    int tsum = s012 + d.w;
    int inc = tsum;
    #pragma unroll
    for (int o = 1; o < 32; o <<= 1) {
        int u = __shfl_up_sync(FULLMASK, inc, o);
        if (lane >= o) inc += u;
    }
    if (lane == 31) wtot[w] = inc;
    __syncthreads();
    if (w == 0 && lane < 8) {
        int v = wtot[lane];
        int s = v;
        #pragma unroll
        for (int o = 1; o < 8; o <<= 1) {
            int u = __shfl_up_sync(0xffu, s, o);
            if (lane >= o) s += u;
        }
        wpre[lane] = s - v;
    }
    __syncthreads();
    int excl = inc - tsum + wpre[w] + g_bpre[b];
    int idx = b * 1024 + tid * 4;
    if (idx     <= n) { g_off[idx]     = excl;        g_woff[idx]     = excl; }
    if (idx + 1 <= n) { g_off[idx + 1] = excl + s0;   g_woff[idx + 1] = excl + s0; }
    if (idx + 2 <= n) { g_off[idx + 2] = excl + s01;  g_woff[idx + 2] = excl + s01; }
    if (idx + 3 <= n) { g_off[idx + 3] = excl + s012; g_woff[idx + 3] = excl + s012; }
}

__global__ void k_scatter(const int* __restrict__ ei, int E) {
    int e = blockIdx.x * blockDim.x + threadIdx.x;
    if (e < E) {
        int dst = ei[E + e];
        int pos = atomicAdd(&g_woff[dst], 1);
        g_perm[pos] = e;
    }
}

// ---------------- fused score + softmax + aggregation + BN stats -------------
__device__ __forceinline__ void edge_compute(
    const float* eew, float4 xlv, float4 xrv, float4 a4,
    const ull (&wreg)[8][4], float4 &acc, float &ds)
{
    ull p0 = 0, p1 = 0, p2 = 0, p3 = 0;
    #pragma unroll
    for (int dp = 0; dp < 8; dp++) {
        ull a = *(const ull*)(eew + 2 * dp);   // smem broadcast
        fma2(p0, a, wreg[dp][0]);
        fma2(p1, a, wreg[dp][1]);
        fma2(p2, a, wreg[dp][2]);
        fma2(p3, a, wreg[dp][3]);
    }
    F2U u0, u1, u2, u3;
    u0.u = p0; u1.u = p1; u2.u = p2; u3.u = p3;
    float mx = xlv.x + xrv.x + u0.f.x + u0.f.y;
    float my = xlv.y + xrv.y + u1.f.x + u1.f.y;
    float mz = xlv.z + xrv.z + u2.f.x + u2.f.y;
    float mw = xlv.w + xrv.w + u3.f.x + u3.f.y;
    mx = mx > 0.f ? mx : 0.2f * mx;
    my = my > 0.f ? my : 0.2f * my;
    mz = mz > 0.f ? mz : 0.2f * mz;
    mw = mw > 0.f ? mw : 0.2f * mw;
    float s = mx * a4.x + my * a4.y + mz * a4.z + mw * a4.w;
    s += __shfl_xor_sync(FULLMASK, s, 1);
    s += __shfl_xor_sync(FULLMASK, s, 2);
    float w = __expf(s);
    ds += w;
    acc.x = fmaf(w, xlv.x, acc.x);
    acc.y = fmaf(w, xlv.y, acc.y);
    acc.z = fmaf(w, xlv.z, acc.z);
    acc.w = fmaf(w, xlv.w, acc.w);
}

#define EDGE_STAGE(Q)                                                          \
    {                                                                          \
        const float* ep = sew + j * EDIM;                                      \
        float4 xlv = Q;                                                        \
        if (j + 4 < m) {                                                       \
            int s4i = __shfl_sync(FULLMASK, sL, j + 4);                        \
            Q = *(const float4*)(g_xl + (size_t)s4i * DD + col);               \
        }                                                                      \
        edge_compute(ep, xlv, xrv, a4, wreg, acc, ds);                         \
        j++;                                                                   \
    }

__global__ __launch_bounds__(128, 4) void k_fused(
    const int* __restrict__ ei, const float* __restrict__ ew,
    const float* __restrict__ We, const float* __restrict__ att,
    const float* __restrict__ bias, float* __restrict__ out, int n)
{
    __shared__ float sew_all[4][32 * EDIM];   // 8 KB
    __shared__ float ssum[4][DD], ssq[4][DD]; // 4 KB
    int lane = threadIdx.x & 31;
    int wid  = threadIdx.x >> 5;
    float* sew = sew_all[wid];
    int gw = blockIdx.x * 4 + wid;
    int nw = gridDim.x * 4;
    int col = lane * 4;

    ull wreg[8][4];
    #pragma unroll
    for (int dp = 0; dp < 8; dp++) {
        #pragma unroll
        for (int c = 0; c < 4; c++) {
            F2U t;
            t.f.x = __ldg(We + (2 * dp)     * DD + col + c);
            t.f.y = __ldg(We + (2 * dp + 1) * DD + col + c);
            wreg[dp][c] = t.u;
        }
    }
    float4 a4 = ((const float4*)att)[lane];
    float4 b4 = ((const float4*)bias)[lane];
    float4 sacc = make_float4(0.f, 0.f, 0.f, 0.f);
    float4 qacc = make_float4(0.f, 0.f, 0.f, 0.f);

    for (int v = gw; v < n; v += nw) {
        int start = g_off[v];
        int end   = g_off[v + 1];
        float4 xrv = *(const float4*)(g_xr + (size_t)v * DD + col);
        float4 acc = make_float4(0.f, 0.f, 0.f, 0.f);
        float ds = 0.f;

        for (int c0 = start; c0 < end; c0 += 32) {
            int m = min(32, end - c0);
            int sL = 0;
            if (lane < m) {
                int eL = g_perm[c0 + lane];
                sL = __ldg(ei + eL);
                const float4* src = (const float4*)(ew + (size_t)eL * EDIM);
                float4* dst = (float4*)(sew + lane * EDIM);
                dst[0] = src[0]; dst[1] = src[1]; dst[2] = src[2]; dst[3] = src[3];
            }
            __syncwarp();

            int s0 = __shfl_sync(FULLMASK, sL, 0);
            int s1 = __shfl_sync(FULLMASK, sL, 1);
            int s2 = __shfl_sync(FULLMASK, sL, 2);
            int s3 = __shfl_sync(FULLMASK, sL, 3);
            float4 xq0 = *(const float4*)(g_xl + (size_t)s0 * DD + col);
            float4 xq1 = *(const float4*)(g_xl + (size_t)s1 * DD + col);
            float4 xq2 = *(const float4*)(g_xl + (size_t)s2 * DD + col);
            float4 xq3 = *(const float4*)(g_xl + (size_t)s3 * DD + col);

            int j = 0;
            while (j < m) {
                EDGE_STAGE(xq0)
                if (j >= m) break;
                EDGE_STAGE(xq1)
                if (j >= m) break;
                EDGE_STAGE(xq2)
                if (j >= m) break;
                EDGE_STAGE(xq3)
            }
            __syncwarp();
        }
        float invd = (end > start) ? 1.f / ds : 0.f;
        float4 o = make_float4(fmaf(acc.x, invd, b4.x), fmaf(acc.y, invd, b4.y),
                               fmaf(acc.z, invd, b4.z), fmaf(acc.w, invd, b4.w));
        *(float4*)(out + (size_t)v * DD + col) = o;
        sacc.x += o.x; sacc.y += o.y; sacc.z += o.z; sacc.w += o.w;
        qacc.x = fmaf(o.x, o.x, qacc.x);
        qacc.y = fmaf(o.y, o.y, qacc.y);
        qacc.z = fmaf(o.z, o.z, qacc.z);
        qacc.w = fmaf(o.w, o.w, qacc.w);
    }

    *(float4*)&ssum[wid][col] = sacc;
    *(float4*)&ssq[wid][col]  = qacc;
    __syncthreads();
    int ch = threadIdx.x;
    float s = ssum[0][ch] + ssum[1][ch] + ssum[2][ch] + ssum[3][ch];
    float q = ssq[0][ch]  + ssq[1][ch]  + ssq[2][ch]  + ssq[3][ch];
    atomicAdd(&g_sum[ch], s);
    atomicAdd(&g_sumsq[ch], q);
}

// ---------------- BN finalize + apply ----------------
__global__ void k_finalize(const float* __restrict__ gamma, const float* __restrict__ beta, int n) {
    int t = threadIdx.x;
    if (t < DD) {
        float invn = 1.f / (float)n;
        float mean = g_sum[t] * invn;
        float var  = g_sumsq[t] * invn - mean * mean;
        if (var < 0.f) var = 0.f;
        float inv = rsqrtf(var + 1e-5f);
        float sc = gamma[t] * inv;
        g_scale[t] = sc;
        g_shift[t] = beta[t] - mean * sc;
    }
}

__global__ void k_apply(float* __restrict__ out, int n) {
    int i = blockIdx.x * blockDim.x + threadIdx.x;
    int total = n * (DD / 4);
    if (i < total) {
        float4 v = ((float4*)out)[i];
        float4 sc = ((float4*)g_scale)[i & 31];
        float4 sh = ((float4*)g_shift)[i & 31];
        float yx = fmaf(v.x, sc.x, sh.x);
        float yy = fmaf(v.y, sc.y, sh.y);
        float yz = fmaf(v.z, sc.z, sh.z);
        float yw = fmaf(v.w, sc.w, sh.w);
        v.x = yx > 0.f ? yx : 0.01f * yx;
        v.y = yy > 0.f ? yy : 0.01f * yy;
        v.z = yz > 0.f ? yz : 0.01f * yz;
        v.w = yw > 0.f ? yw : 0.01f * yw;
        ((float4*)out)[i] = v;
    }
}

// ---------------- launch ----------------
extern "C" void kernel_launch(void* const* d_in, const int* in_sizes, int n_in,
                              void* d_out, int out_size)
{
    const int*   x     = (const int*)  d_in[0];
    const int*   ei    = (const int*)  d_in[1];
    const float* ew    = (const float*)d_in[2];
    const float* emb   = (const float*)d_in[3];
    const float* Wl    = (const float*)d_in[4];
    const float* bl    = (const float*)d_in[5];
    const float* Wr    = (const float*)d_in[6];
    const float* br    = (const float*)d_in[7];
    const float* att   = (const float*)d_in[8];
    const float* We    = (const float*)d_in[9];
    const float* bias  = (const float*)d_in[10];
    const float* gamma = (const float*)d_in[11];
    const float* beta  = (const float*)d_in[12];
    float* out = (float*)d_out;

    int n = in_sizes[0];
    int E = in_sizes[1] / 2;
    int nb = (n + 1023) / 1024;

    k_zero<<<96, 256>>>(n);
    k_hist<<<(E + 255) / 256, 256>>>(ei, E);
    k_packW<<<128, 256>>>(Wl, Wr);

    k_node<<<296, 256>>>(x, emb, bl, br, n);   // 4th launch -> ncu capture

    k_bsum<<<nb, 256>>>();
    k_bscan<<<1, 64>>>(nb);
    k_off<<<nb, 256>>>(n);
    k_scatter<<<(E + 255) / 256, 256>>>(ei, E);

    k_fused<<<592, 128>>>(ei, ew, We, att, bias, out, n);

    k_finalize<<<1, 128>>>(gamma, beta, n);
    k_apply<<<(n * (DD / 4) + 255) / 256, 256>>>(out, n);
}